// round 1
// baseline (speedup 1.0000x reference)
#include <cuda_runtime.h>
#include <math.h>

#define Bsz   8192
#define Ddim  512
#define Kneg  2048
#define NPAD  4096
#define EPSN  1e-8f

// ---------------- scratch (static device globals; no allocation) ----------------
__device__ float g_C[(size_t)Bsz * NPAD];     // gathered-GEMM output (raw dots)
__device__ float g_ni[Bsz], g_nj[Bsz], g_plog[Bsz];
__device__ int   g_mark[Bsz], g_slot[Bsz];
__device__ int   g_Ulist[NPAD];
__device__ int   g_map0[Kneg], g_map1[Kneg];
__device__ float g_nj0[Kneg], g_nj1[Kneg];
__device__ int   g_Ucnt;
__device__ float g_loss[Bsz];
__device__ int   g_cnt[Bsz];

// ---------------- 0. zero the mark array (graph-replay safe) ----------------
__global__ void zero_mark_kernel() {
    int i = blockIdx.x * blockDim.x + threadIdx.x;
    if (i < Bsz) g_mark[i] = 0;
}

// ---------------- 1. norms + positive logit (one warp per row) ----------------
__global__ void norms_kernel(const float* __restrict__ zi, const float* __restrict__ zj) {
    int warp = (blockIdx.x * blockDim.x + threadIdx.x) >> 5;
    int lane = threadIdx.x & 31;
    if (warp >= Bsz) return;
    const float4* a = (const float4*)(zi + (size_t)warp * Ddim);
    const float4* b = (const float4*)(zj + (size_t)warp * Ddim);
    float si = 0.f, sj = 0.f, dij = 0.f;
#pragma unroll
    for (int c = 0; c < 4; c++) {
        float4 x = a[c * 32 + lane];
        float4 y = b[c * 32 + lane];
        si  += x.x*x.x + x.y*x.y + x.z*x.z + x.w*x.w;
        sj  += y.x*y.x + y.y*y.y + y.z*y.z + y.w*y.w;
        dij += x.x*y.x + x.y*y.y + x.z*y.z + x.w*y.w;
    }
#pragma unroll
    for (int o = 16; o > 0; o >>= 1) {
        si  += __shfl_down_sync(0xffffffffu, si, o);
        sj  += __shfl_down_sync(0xffffffffu, sj, o);
        dij += __shfl_down_sync(0xffffffffu, dij, o);
    }
    if (lane == 0) {
        float ni = sqrtf(si), nj = sqrtf(sj);
        g_ni[warp] = ni;
        g_nj[warp] = nj;
        g_plog[warp] = dij / fmaxf(ni * nj, EPSN) * 2.0f;   // /T, T=0.5
    }
}

// ---------------- 2a. scatter marks for union {p} u {p+1} ----------------
__global__ void scatter_kernel(const int* __restrict__ perm) {
    int k = blockIdx.x * blockDim.x + threadIdx.x;
    if (k < Kneg) {
        int p = perm[k];
        g_mark[p] = 1;
        g_mark[p + 1] = 1;
    }
}

// ---------------- 2b. exclusive scan over marks (one block, deterministic) ----------------
__global__ void scan_kernel() {
    __shared__ int ssum[1024];
    int tid = threadIdx.x;
    int base = tid * 8;
    int v[8], pre[8];
    int s = 0;
#pragma unroll
    for (int j = 0; j < 8; j++) {
        v[j] = g_mark[base + j];
        pre[j] = s;
        s += v[j];
    }
    ssum[tid] = s;
    __syncthreads();
    for (int off = 1; off < 1024; off <<= 1) {
        int t = (tid >= off) ? ssum[tid - off] : 0;
        __syncthreads();
        ssum[tid] += t;
        __syncthreads();
    }
    int excl = ssum[tid] - s;
#pragma unroll
    for (int j = 0; j < 8; j++) g_slot[base + j] = excl + pre[j];
    if (tid == 1023) g_Ucnt = ssum[1023];
}

// ---------------- 2c. build U list (+pad) ----------------
__global__ void build_kernel() {
    int j = blockIdx.x * blockDim.x + threadIdx.x;
    if (j < Bsz && g_mark[j]) g_Ulist[g_slot[j]] = j;
    if (j < NPAD && j >= g_Ucnt) g_Ulist[j] = 0;   // disjoint slots; no race
}

// ---------------- 2d. per-k slot + norm maps ----------------
__global__ void maps_kernel(const int* __restrict__ perm) {
    int k = blockIdx.x * blockDim.x + threadIdx.x;
    if (k < Kneg) {
        int p = perm[k];
        g_map0[k] = g_slot[p];
        g_map1[k] = g_slot[p + 1];
        g_nj0[k] = g_nj[p];
        g_nj1[k] = g_nj[p + 1];
    }
}

// ---------------- 3. gathered SGEMM: C[m,u] = z_i[m] . z_j[Ulist[u]] ----------------
// 128x128 block tile, TK=16, 256 threads, 8x8 per thread.
__global__ __launch_bounds__(256) void gemm_kernel(const float* __restrict__ A,
                                                   const float* __restrict__ Zj) {
    const int n0 = blockIdx.x * 128;
    const int m0 = blockIdx.y * 128;
    if (n0 >= g_Ucnt) return;   // columns beyond the union are never read

    __shared__ float As[16][128];
    __shared__ float Bs[16][128];

    const int tid  = threadIdx.x;
    const int lrow = tid >> 1;          // 0..127
    const int lk   = (tid & 1) * 8;     // 0 or 8
    const int tx   = tid & 15;
    const int ty   = tid >> 4;

    const int urow = g_Ulist[n0 + lrow];                 // gather row for B operand
    const float* pA = A  + (size_t)(m0 + lrow) * Ddim + lk;
    const float* pB = Zj + (size_t)urow * Ddim + lk;

    float acc[8][8];
#pragma unroll
    for (int i = 0; i < 8; i++)
#pragma unroll
        for (int j = 0; j < 8; j++) acc[i][j] = 0.f;

    for (int k0 = 0; k0 < Ddim; k0 += 16) {
        float4 a0 = *(const float4*)(pA + k0);
        float4 a1 = *(const float4*)(pA + k0 + 4);
        float4 b0 = *(const float4*)(pB + k0);
        float4 b1 = *(const float4*)(pB + k0 + 4);
        As[lk + 0][lrow] = a0.x; As[lk + 1][lrow] = a0.y;
        As[lk + 2][lrow] = a0.z; As[lk + 3][lrow] = a0.w;
        As[lk + 4][lrow] = a1.x; As[lk + 5][lrow] = a1.y;
        As[lk + 6][lrow] = a1.z; As[lk + 7][lrow] = a1.w;
        Bs[lk + 0][lrow] = b0.x; Bs[lk + 1][lrow] = b0.y;
        Bs[lk + 2][lrow] = b0.z; Bs[lk + 3][lrow] = b0.w;
        Bs[lk + 4][lrow] = b1.x; Bs[lk + 5][lrow] = b1.y;
        Bs[lk + 6][lrow] = b1.z; Bs[lk + 7][lrow] = b1.w;
        __syncthreads();
#pragma unroll
        for (int kk = 0; kk < 16; kk++) {
            float4 aL = *(const float4*)&As[kk][ty * 8];
            float4 aH = *(const float4*)&As[kk][ty * 8 + 4];
            float4 bL = *(const float4*)&Bs[kk][tx * 8];
            float4 bH = *(const float4*)&Bs[kk][tx * 8 + 4];
            float av[8] = {aL.x, aL.y, aL.z, aL.w, aH.x, aH.y, aH.z, aH.w};
            float bv[8] = {bL.x, bL.y, bL.z, bL.w, bH.x, bH.y, bH.z, bH.w};
#pragma unroll
            for (int i = 0; i < 8; i++)
#pragma unroll
                for (int j = 0; j < 8; j++) acc[i][j] += av[i] * bv[j];
        }
        __syncthreads();
    }

#pragma unroll
    for (int i = 0; i < 8; i++) {
        float* pC = g_C + (size_t)(m0 + ty * 8 + i) * NPAD + n0 + tx * 8;
        *(float4*)(pC)     = make_float4(acc[i][0], acc[i][1], acc[i][2], acc[i][3]);
        *(float4*)(pC + 4) = make_float4(acc[i][4], acc[i][5], acc[i][6], acc[i][7]);
    }
}

// ---------------- 4. per-row logsumexp + rank counts (8 rows per block) ----------------
__global__ __launch_bounds__(256) void reduce_kernel(const int* __restrict__ perm) {
    __shared__ int   s_p[Kneg];
    __shared__ int   s_m0[Kneg];
    __shared__ int   s_m1[Kneg];
    __shared__ float s_n0[Kneg];
    __shared__ float s_n1[Kneg];
    __shared__ float redf[256];
    __shared__ int   redi[256];

    int tid = threadIdx.x;
    for (int k = tid; k < Kneg; k += 256) {
        s_p[k]  = perm[k];
        s_m0[k] = g_map0[k];
        s_m1[k] = g_map1[k];
        s_n0[k] = g_nj0[k];
        s_n1[k] = g_nj1[k];
    }
    __syncthreads();

    for (int r = 0; r < 8; r++) {
        int i = blockIdx.x * 8 + r;
        float ni = g_ni[i];
        float lp = g_plog[i];
        const float* Crow = g_C + (size_t)i * NPAD;

        // pass 1: max
        float tmax = lp;
        for (int k = tid; k < Kneg; k += 256) {
            bool sel = (s_p[k] >= i);
            int slot  = sel ? s_m1[k] : s_m0[k];
            float njc = sel ? s_n1[k] : s_n0[k];
            float l = Crow[slot] / fmaxf(ni * njc, EPSN) * 2.0f;
            tmax = fmaxf(tmax, l);
        }
        redf[tid] = tmax;
        __syncthreads();
        for (int o = 128; o > 0; o >>= 1) {
            if (tid < o) redf[tid] = fmaxf(redf[tid], redf[tid + o]);
            __syncthreads();
        }
        float M = redf[0];
        __syncthreads();

        // pass 2: sum exp + count(neg > pos)
        float s = 0.f;
        int cnt = 0;
        for (int k = tid; k < Kneg; k += 256) {
            bool sel = (s_p[k] >= i);
            int slot  = sel ? s_m1[k] : s_m0[k];
            float njc = sel ? s_n1[k] : s_n0[k];
            float l = Crow[slot] / fmaxf(ni * njc, EPSN) * 2.0f;
            s += expf(l - M);
            cnt += (l > lp) ? 1 : 0;
        }
        redf[tid] = s;
        redi[tid] = cnt;
        __syncthreads();
        for (int o = 128; o > 0; o >>= 1) {
            if (tid < o) { redf[tid] += redf[tid + o]; redi[tid] += redi[tid + o]; }
            __syncthreads();
        }
        if (tid == 0) {
            g_loss[i] = M + logf(redf[0] + expf(lp - M)) - lp;
            g_cnt[i]  = redi[0];
        }
        __syncthreads();
    }
}

// ---------------- 5. deterministic final reduction ----------------
__global__ void final_kernel(float* __restrict__ out) {
    __shared__ float sf[1024];
    __shared__ int   s1[1024];
    __shared__ int   s5[1024];
    int tid = threadIdx.x;
    float s = 0.f;
    int c1 = 0, c5 = 0;
    for (int i = tid; i < Bsz; i += 1024) {
        s += g_loss[i];
        int c = g_cnt[i];
        c1 += (c == 0) ? 1 : 0;
        c5 += (c <= 4) ? 1 : 0;
    }
    sf[tid] = s; s1[tid] = c1; s5[tid] = c5;
    __syncthreads();
    for (int o = 512; o > 0; o >>= 1) {
        if (tid < o) { sf[tid] += sf[tid + o]; s1[tid] += s1[tid + o]; s5[tid] += s5[tid + o]; }
        __syncthreads();
    }
    if (tid == 0) {
        out[0] = sf[0] / (float)Bsz;
        out[1] = 100.0f * (float)s1[0] / (float)Bsz;
        out[2] = 100.0f * (float)s5[0] / (float)Bsz;
    }
}

// ---------------- launch ----------------
extern "C" void kernel_launch(void* const* d_in, const int* in_sizes, int n_in,
                              void* d_out, int out_size) {
    const float* zi   = (const float*)d_in[0];
    const float* zj   = (const float*)d_in[1];
    const int*   perm = (const int*)d_in[2];
    float* out = (float*)d_out;

    zero_mark_kernel<<<8, 1024>>>();
    norms_kernel<<<Bsz / 8, 256>>>(zi, zj);          // 1 warp per row
    scatter_kernel<<<2, 1024>>>(perm);
    scan_kernel<<<1, 1024>>>();
    build_kernel<<<8, 1024>>>();
    maps_kernel<<<2, 1024>>>(perm);

    dim3 g(NPAD / 128, Bsz / 128);                   // 32 x 64 blocks
    gemm_kernel<<<g, 256>>>(zi, zj);

    reduce_kernel<<<Bsz / 8, 256>>>(perm);
    final_kernel<<<1, 1024>>>(out);
}